// round 10
// baseline (speedup 1.0000x reference)
#include <cuda_runtime.h>
#include <math.h>

#define BDIM 256            // 2 threads per angle -> 128 angles per block
#define NPTS 64
#define HALF_PTS 32
#define PI_F      3.14159265358979f
#define INV_PI_F  0.318309886183791f
#define MAGIC_F   12582912.0f
#define EPS_U     3.1830989e-5f   // 1e-4 / pi
#define MAX_N     16384

// Per-angle constants: {qx/pi, qy/pi, -qy/pi, scale}
__device__ float4 g_cst[MAX_N];

__device__ __forceinline__ float rcp_approx(float x) {
    float r; asm("rcp.approx.f32 %0, %1;" : "=f"(r) : "f"(x)); return r;
}

// ---------------- setup kernel: once per graph replay, ~0.5us ---------------
__global__ void setup_kernel(const float* __restrict__ phi, int N) {
    const int n = blockIdx.x * blockDim.x + threadIdx.x;
    if (n >= N) return;
    float s, c;
    sincosf(phi[n], &s, &c);        // accurate: phi ~ pi/2 -> |q| tiny, scale huge
    const float qx = c;
    const float qy = s - 1.0f;
    const float scale = 1.0f / fabsf(qx * qx + qy * qy);
    g_cst[n] = make_float4(qx * INV_PI_F, qy * INV_PI_F, -qy * INV_PI_F, scale);
}

// ---------------- main kernel ----------------------------------------------
__global__ __launch_bounds__(BDIM)
void scatter_polygon_kernel(const float* __restrict__ points,
                            float* __restrict__ out,
                            int B, int N) {
    __shared__ float4 spts[NPTS / 2];   // two points per float4

    const int b = blockIdx.y;
    const int tid = threadIdx.x;
    const int alocal = tid >> 1;        // angle within block (0..127)
    const int h = tid & 1;              // which half of the edge loop
    const int n = blockIdx.x * (BDIM / 2) + alocal;

    if (tid < 2 * NPTS) {
        reinterpret_cast<float*>(spts)[tid] = points[b * 2 * NPTS + tid];
    }
    __syncthreads();

    if (n >= N) return;                 // N multiple of 128 -> uniform per warp

    // Per-angle constants: one 16B load (pairs share it; L1 broadcast).
    const float4 cst = g_cst[n];
    const float qxp  = cst.x;
    const float qyp  = cst.y;
    const float nqyp = cst.z;
    const float scale = cst.w;

    // Scalar eval: u = (p.q)/pi, hc = (p.q_cross)/pi, (s,c) = sincos(p.q)
    // via mod-pi reduction; truncated Taylor of sin(pi f)/cos(pi f) in f.
    // Leading terms exact -> relative accuracy preserved for small args;
    // truncation <= 3.6e-6 only near |f|=0.5 where values are O(1).
    auto eval1 = [&](float px, float py,
                     float& u, float& hc, float& s, float& c) {
        u  = fmaf(px, qxp, py * qyp);
        hc = fmaf(py, qxp, px * nqyp);
        const float t  = u + MAGIC_F;
        const float nf = t - MAGIC_F;         // round(u)
        const float f  = u - nf;              // exact (Sterbenz)
        const float f2 = f * f;

        float w = fmaf(f2, 0.08214589f, -0.59926453f);
        w = fmaf(f2, w, 2.55016404f);
        w = fmaf(f2, w, -5.16771278f);
        w = fmaf(f2, w, 3.14159265f);
        const float sp = f * w;               // sin(pi f), deg 9

        float v = fmaf(f2, -2.5806891e-2f, 0.23533063f);
        v = fmaf(f2, v, -1.33526277f);
        v = fmaf(f2, v, 4.05871213f);
        v = fmaf(f2, v, -4.93480220f);
        const float cp = fmaf(f2, v, 1.0f);   // cos(pi f), deg 10

        const int g = __float_as_int(t) << 31;   // (-1)^n sign bit
        s = __int_as_float(__float_as_int(sp) ^ g);
        c = __int_as_float(__float_as_int(cp) ^ g);
    };

    float sum_r = 0.0f, nsum_i = 0.0f;        // nsum_i accumulates -imag

    // This thread covers edges [h*32, h*32+32); prev point = h*32-1 mod 64.
    const int pstart = h * HALF_PTS;
    const int pprev  = (pstart + NPTS - 1) & (NPTS - 1);   // 63 or 31 (odd)

    float up, hp, sprev, cprev;
    {
        const float4 pl = spts[pprev >> 1];   // odd index -> .zw
        eval1(pl.z, pl.w, up, hp, sprev, cprev);
    }

    // edge (prev -> cur): shared multiplier select, negated-imag accumulation.
    //  case1 (|ddq|>=eps): r += g*(cprev-cc);  -i += g*(sc-sprev)
    //  case2:              r += dq*sprev;      -i += dq*cprev   (dq = ddqc)
    auto edge = [&](float uc, float hc, float sc, float cc) {
        const float du = uc - up;             // ddq / pi
        const float dc = hc - hp;             // ddqc / pi
        const float g  = dc * rcp_approx(du); // ddqc / ddq
        const float dq = PI_F * dc;           // ddqc
        const bool big = fabsf(du) >= EPS_U;
        const float f  = big ? g : dq;
        const float vr = big ? (cprev - cc) : sprev;
        const float vi = big ? (sc - sprev) : cprev;
        sum_r  = fmaf(f, vr, sum_r);
        nsum_i = fmaf(f, vi, nsum_i);
        up = uc; hp = hc; sprev = sc; cprev = cc;
    };

    const int kk0 = pstart >> 1;
#pragma unroll 8
    for (int kk = 0; kk < HALF_PTS / 2; ++kk) {
        const float4 pc = spts[kk0 + kk];     // two consecutive points
        float u0, h0, s0, c0, u1, h1, s1, c1;
        eval1(pc.x, pc.y, u0, h0, s0, c0);    // independent scalar chains
        eval1(pc.z, pc.w, u1, h1, s1, c1);
        edge(u0, h0, s0, c0);
        edge(u1, h1, s1, c1);
    }

    // Combine halves (pair = lanes 2t, 2t+1 of the same warp).
    sum_r  += __shfl_xor_sync(0xFFFFFFFF, sum_r, 1);
    nsum_i += __shfl_xor_sync(0xFFFFFFFF, nsum_i, 1);

    if (h == 0) {
        out[(b * 2 + 0) * N + n] = scale * sum_r;
        out[(b * 2 + 1) * N + n] = -(scale * nsum_i);
    }
}

extern "C" void kernel_launch(void* const* d_in, const int* in_sizes, int n_in,
                              void* d_out, int out_size) {
    const float* points = (const float*)d_in[0];  // [B, 64, 2] f32
    const float* phi    = (const float*)d_in[1];  // [N] f32
    float* out = (float*)d_out;                   // [B, 2, N] f32

    const int N = in_sizes[1];
    const int B = in_sizes[0] / (2 * NPTS);

    setup_kernel<<<(N + 255) / 256, 256>>>(phi, N);

    const int angles_per_block = BDIM / 2;
    dim3 grid((N + angles_per_block - 1) / angles_per_block, B);
    scatter_polygon_kernel<<<grid, BDIM>>>(points, out, B, N);
}

// round 12
// speedup vs baseline: 1.1073x; 1.1073x over previous
#include <cuda_runtime.h>
#include <math.h>

#define BDIM 128
#define NPTS 64
#define PI_F      3.14159265358979f
#define INV_PI_F  0.318309886183791f
#define MAGIC_F   12582912.0f
#define EPS_U     3.1830989e-5f   // 1e-4 / pi

__device__ __forceinline__ float rcp_approx(float x) {
    float r; asm("rcp.approx.f32 %0, %1;" : "=f"(r) : "f"(x)); return r;
}

__global__ __launch_bounds__(BDIM)
void scatter_polygon_kernel(const float* __restrict__ points,
                            const float* __restrict__ phi,
                            float* __restrict__ out,
                            int B, int N) {
    __shared__ float4 spts[NPTS / 2];   // two points per float4

    const int b = blockIdx.y;
    const int n = blockIdx.x * BDIM + threadIdx.x;

    reinterpret_cast<float*>(spts)[threadIdx.x] = points[b * 2 * NPTS + threadIdx.x];
    __syncthreads();

    if (n >= N) return;

    // Per-angle constants — accurate libm sincos (phi ~ pi/2 -> |q| tiny,
    // scale huge; needs exact reduction), once per thread.
    float sphi, cphi;
    sincosf(phi[n], &sphi, &cphi);
    const float qx = cphi;
    const float qy = sphi - 1.0f;
    const float scale = 1.0f / fabsf(qx * qx + qy * qy);
    const float qxp = qx * INV_PI_F;
    const float qyp = qy * INV_PI_F;
    const float nqyp = -qyp;

    // Scalar eval: u = (p.q)/pi, hc = (p.q_cross)/pi, (s,c) = sincos(p.q)
    // via mod-pi reduction; truncated Taylor of sin(pi f) (deg 9) and
    // cos(pi f) (deg 10) in f, pi folded into coefficients. Leading terms
    // exact -> relative accuracy preserved for small arguments; truncation
    // <= ~3.6e-6 only near |f| = 0.5 where the values are O(1).
    auto eval1 = [&](float px, float py,
                     float& u, float& hc, float& s, float& c) {
        u  = fmaf(px, qxp, py * qyp);
        hc = fmaf(py, qxp, px * nqyp);
        const float t  = u + MAGIC_F;
        const float nf = t - MAGIC_F;         // round(u)
        const float f  = u - nf;              // exact (Sterbenz)
        const float f2 = f * f;

        float w = fmaf(f2, 0.0821458866f, -0.599264529f);
        w = fmaf(f2, w, 2.55016404f);
        w = fmaf(f2, w, -5.16771278f);
        w = fmaf(f2, w, 3.14159265f);
        const float sp = f * w;               // sin(pi f), deg 9

        float v = fmaf(f2, -2.5806891e-2f, 0.23533063f);
        v = fmaf(f2, v, -1.33526277f);
        v = fmaf(f2, v, 4.05871213f);
        v = fmaf(f2, v, -4.93480220f);
        const float cp = fmaf(f2, v, 1.0f);   // cos(pi f), deg 10

        const int g = __float_as_int(t) << 31;   // (-1)^n sign bit
        s = __int_as_float(__float_as_int(sp) ^ g);
        c = __int_as_float(__float_as_int(cp) ^ g);
    };

    float sum_r = 0.0f, nsum_i = 0.0f;        // nsum_i accumulates -imag

    // prev = point[NPTS-1]
    float up, hp, sprev, cprev;
    {
        const float4 pl = spts[NPTS / 2 - 1];
        eval1(pl.z, pl.w, up, hp, sprev, cprev);
    }

    // edge (prev -> cur). One select chooses the multiplier:
    //  case1 (|ddq|>=eps): f = dc*rcp(du) = ddqc/ddq;  r += f*(cprev-cc), -i += f*(sc-sprev)
    //  case2:              f = dc*pi      = ddqc;      r += f*sprev,      -i += f*cprev
    auto edge = [&](float uc, float hc, float sc, float cc) {
        const float du = uc - up;             // ddq / pi
        const float dc = hc - hp;             // ddqc / pi
        const float rin = rcp_approx(du);
        const bool big = fabsf(du) >= EPS_U;
        const float m  = big ? rin : PI_F;
        const float f  = dc * m;
        const float vr = big ? (cprev - cc) : sprev;
        const float vi = big ? (sc - sprev) : cprev;
        sum_r  = fmaf(f, vr, sum_r);
        nsum_i = fmaf(f, vi, nsum_i);
        up = uc; hp = hc; sprev = sc; cprev = cc;
    };

#pragma unroll
    for (int kk = 0; kk < NPTS / 2; ++kk) {   // fully unrolled, 16 iterations
        const float4 pc = spts[kk];           // points 2kk (x,y), 2kk+1 (z,w)
        float u0, h0, s0, c0, u1, h1, s1, c1;
        eval1(pc.x, pc.y, u0, h0, s0, c0);    // two independent scalar chains
        eval1(pc.z, pc.w, u1, h1, s1, c1);
        edge(u0, h0, s0, c0);
        edge(u1, h1, s1, c1);
    }

    out[(b * 2 + 0) * N + n] = scale * sum_r;
    out[(b * 2 + 1) * N + n] = -(scale * nsum_i);
}

extern "C" void kernel_launch(void* const* d_in, const int* in_sizes, int n_in,
                              void* d_out, int out_size) {
    const float* points = (const float*)d_in[0];  // [B, 64, 2] f32
    const float* phi    = (const float*)d_in[1];  // [N] f32
    float* out = (float*)d_out;                   // [B, 2, N] f32

    const int N = in_sizes[1];
    const int B = in_sizes[0] / (2 * NPTS);

    dim3 grid((N + BDIM - 1) / BDIM, B);
    scatter_polygon_kernel<<<grid, BDIM>>>(points, phi, out, B, N);
}

// round 13
// speedup vs baseline: 1.1186x; 1.0102x over previous
#include <cuda_runtime.h>
#include <math.h>

#define BDIM 128
#define NPTS 64
#define PI_F      3.14159265358979f
#define INV_PI_F  0.318309886183791f
#define MAGIC_F   12582912.0f
#define EPS_U     3.1830989e-5f   // 1e-4 / pi

__device__ __forceinline__ float rcp_approx(float x) {
    float r; asm("rcp.approx.f32 %0, %1;" : "=f"(r) : "f"(x)); return r;
}

__global__ __launch_bounds__(BDIM)
void scatter_polygon_kernel(const float* __restrict__ points,
                            const float* __restrict__ phi,
                            float* __restrict__ out,
                            int B, int N) {
    __shared__ float4 spts[NPTS / 2];   // two points per float4

    const int b = blockIdx.y;
    const int n = blockIdx.x * BDIM + threadIdx.x;

    reinterpret_cast<float*>(spts)[threadIdx.x] = points[b * 2 * NPTS + threadIdx.x];
    __syncthreads();

    if (n >= N) return;

    // Per-angle constants — accurate libm sincos (phi ~ pi/2 -> |q| tiny,
    // scale ~ 1/delta^2 huge; q must be accurate to ~1e-7 absolute).
    float sphi, cphi;
    sincosf(phi[n], &sphi, &cphi);
    const float qx = cphi;
    const float qy = sphi - 1.0f;
    const float scale = 1.0f / fabsf(qx * qx + qy * qy);
    const float qxp = qx * INV_PI_F;
    const float qyp = qy * INV_PI_F;
    const float nqyp = -qyp;

    // Scalar eval: u = (p.q)/pi, hc = (p.q_cross)/pi, (s,c) = sincos(p.q)
    // via mod-pi reduction. Chebyshev-economized polys on f in [-1/2, 1/2]:
    //   sin(pi f): deg-7 (economized from deg-9 Taylor; err <= ~4.2e-6 smooth)
    //   cos(pi f): deg-8 (economized from deg-10 Taylor; err <= ~6e-7 smooth)
    // Smooth error cancels in the edge differences and stays relative; the
    // c1 perturbation (3.6e-6 relative) is multiplicative -> safe near 0.
    auto eval1 = [&](float px, float py,
                     float& u, float& hc, float& s, float& c) {
        u  = fmaf(px, qxp, py * qyp);
        hc = fmaf(py, qxp, px * nqyp);
        const float t  = u + MAGIC_F;
        const float nf = t - MAGIC_F;         // round(u)
        const float f  = u - nf;              // exact (Sterbenz)
        const float f2 = f * f;

        float w = fmaf(f2, -0.55305645f, 2.54150018f);
        w = fmaf(f2, w, -5.16711112f);
        w = fmaf(f2, w, 3.14158137f);
        const float sp = f * w;               // sin(pi f), econ deg 7

        float v = fmaf(f2, 0.21920132f, -1.33173449f);
        v = fmaf(f2, v, 4.05839710f);
        v = fmaf(f2, v, -4.93479236f);
        const float cp = fmaf(f2, v, 1.0f);   // cos(pi f), econ deg 8

        const int g = __float_as_int(t) << 31;   // (-1)^n sign bit
        s = __int_as_float(__float_as_int(sp) ^ g);
        c = __int_as_float(__float_as_int(cp) ^ g);
    };

    float sum_r = 0.0f, nsum_i = 0.0f;        // nsum_i accumulates -imag

    // prev = point[NPTS-1]
    float up, hp, sprev, cprev;
    {
        const float4 pl = spts[NPTS / 2 - 1];
        eval1(pl.z, pl.w, up, hp, sprev, cprev);
    }

    // edge (prev -> cur). One select chooses the multiplier:
    //  case1 (|ddq|>=eps): f = dc*rcp(du) = ddqc/ddq;  r += f*(cprev-cc), -i += f*(sc-sprev)
    //  case2:              f = dc*pi      = ddqc;      r += f*sprev,      -i += f*cprev
    auto edge = [&](float uc, float hc, float sc, float cc) {
        const float du = uc - up;             // ddq / pi
        const float dc = hc - hp;             // ddqc / pi
        const float rin = rcp_approx(du);
        const bool big = fabsf(du) >= EPS_U;
        const float m  = big ? rin : PI_F;
        const float f  = dc * m;
        const float vr = big ? (cprev - cc) : sprev;
        const float vi = big ? (sc - sprev) : cprev;
        sum_r  = fmaf(f, vr, sum_r);
        nsum_i = fmaf(f, vi, nsum_i);
        up = uc; hp = hc; sprev = sc; cprev = cc;
    };

#pragma unroll
    for (int kk = 0; kk < NPTS / 2; ++kk) {   // fully unrolled, 16 iterations
        const float4 pc = spts[kk];           // points 2kk (x,y), 2kk+1 (z,w)
        float u0, h0, s0, c0, u1, h1, s1, c1;
        eval1(pc.x, pc.y, u0, h0, s0, c0);    // two independent scalar chains
        eval1(pc.z, pc.w, u1, h1, s1, c1);
        edge(u0, h0, s0, c0);
        edge(u1, h1, s1, c1);
    }

    out[(b * 2 + 0) * N + n] = scale * sum_r;
    out[(b * 2 + 1) * N + n] = -(scale * nsum_i);
}

extern "C" void kernel_launch(void* const* d_in, const int* in_sizes, int n_in,
                              void* d_out, int out_size) {
    const float* points = (const float*)d_in[0];  // [B, 64, 2] f32
    const float* phi    = (const float*)d_in[1];  // [N] f32
    float* out = (float*)d_out;                   // [B, 2, N] f32

    const int N = in_sizes[1];
    const int B = in_sizes[0] / (2 * NPTS);

    dim3 grid((N + BDIM - 1) / BDIM, B);
    scatter_polygon_kernel<<<grid, BDIM>>>(points, phi, out, B, N);
}

// round 14
// speedup vs baseline: 1.1215x; 1.0026x over previous
#include <cuda_runtime.h>
#include <math.h>

#define BDIM 128
#define NPTS 64
#define PI_F      3.14159265358979f
#define INV_PI_F  0.318309886183791f
#define MAGIC_F   12582912.0f
#define EPS_U     3.1830989e-5f   // 1e-4 / pi

__device__ __forceinline__ float rcp_approx(float x) {
    float r; asm("rcp.approx.f32 %0, %1;" : "=f"(r) : "f"(x)); return r;
}

__global__ __launch_bounds__(BDIM)
void scatter_polygon_kernel(const float* __restrict__ points,
                            const float* __restrict__ phi,
                            float* __restrict__ out,
                            int B, int N) {
    // Two batches staged per block: 2 x 64 points (two points per float4).
    __shared__ float4 spA[NPTS / 2];
    __shared__ float4 spB[NPTS / 2];

    const int bpair = blockIdx.y;           // batch pair index
    const int b0 = 2 * bpair;
    const int b1 = b0 + 1;
    const int n = blockIdx.x * BDIM + threadIdx.x;

    // Stage 256 floats with 128 threads (2 each).
    {
        const float* src = points + b0 * 2 * NPTS;
        float* dst = reinterpret_cast<float*>(spA);   // spA, spB contiguous? no —
        // load each array explicitly (layouts may not be adjacent).
        dst[threadIdx.x] = src[threadIdx.x];
        reinterpret_cast<float*>(spB)[threadIdx.x] = src[2 * NPTS + threadIdx.x];
    }
    __syncthreads();

    if (n >= N) return;

    // Per-angle constants — ONCE for both batches. Accurate libm sincos
    // (phi ~ pi/2 -> |q| tiny, scale ~1/delta^2 huge; needs exact reduction).
    float sphi, cphi;
    sincosf(phi[n], &sphi, &cphi);
    const float qx = cphi;
    const float qy = sphi - 1.0f;
    const float scale = 1.0f / fabsf(qx * qx + qy * qy);
    const float qxp = qx * INV_PI_F;
    const float qyp = qy * INV_PI_F;
    const float nqyp = -qyp;

    // Scalar eval: u = (p.q)/pi, hc = (p.q_cross)/pi, (s,c) = sincos(p.q)
    // via mod-pi reduction; Chebyshev-economized polys on [-1/2, 1/2]
    // (sin deg-7, cos deg-8; smooth error <= ~4e-6, relative-accurate for
    // small args since leading terms are exact).
    auto eval1 = [&](float px, float py,
                     float& u, float& hc, float& s, float& c) {
        u  = fmaf(px, qxp, py * qyp);
        hc = fmaf(py, qxp, px * nqyp);
        const float t  = u + MAGIC_F;
        const float nf = t - MAGIC_F;         // round(u)
        const float f  = u - nf;              // exact (Sterbenz)
        const float f2 = f * f;

        float w = fmaf(f2, -0.55305645f, 2.54150018f);
        w = fmaf(f2, w, -5.16711112f);
        w = fmaf(f2, w, 3.14158137f);
        const float sp = f * w;               // sin(pi f)

        float v = fmaf(f2, 0.21920132f, -1.33173449f);
        v = fmaf(f2, v, 4.05839710f);
        v = fmaf(f2, v, -4.93479236f);
        const float cp = fmaf(f2, v, 1.0f);   // cos(pi f)

        const int g = __float_as_int(t) << 31;   // (-1)^n sign bit
        s = __int_as_float(__float_as_int(sp) ^ g);
        c = __int_as_float(__float_as_int(cp) ^ g);
    };

    // Per-batch running state.
    float upA, hpA, spvA, cpvA, upB, hpB, spvB, cpvB;
    {
        const float4 plA = spA[NPTS / 2 - 1];
        const float4 plB = spB[NPTS / 2 - 1];
        eval1(plA.z, plA.w, upA, hpA, spvA, cpvA);
        eval1(plB.z, plB.w, upB, hpB, spvB, cpvB);
    }

    float sum_rA = 0.0f, nsum_iA = 0.0f;      // nsum accumulates -imag
    float sum_rB = 0.0f, nsum_iB = 0.0f;

    // edge (prev -> cur) for batch A / B; one select picks the multiplier:
    //  case1 (|ddq|>=eps): f = dc*rcp(du);  r += f*(cprev-cc), -i += f*(sc-sprev)
    //  case2:              f = dc*pi;       r += f*sprev,      -i += f*cprev
    auto edgeA = [&](float uc, float hc, float sc, float cc) {
        const float du = uc - upA;
        const float dc = hc - hpA;
        const float rin = rcp_approx(du);
        const bool big = fabsf(du) >= EPS_U;
        const float m  = big ? rin : PI_F;
        const float f  = dc * m;
        const float vr = big ? (cpvA - cc) : spvA;
        const float vi = big ? (sc - spvA) : cpvA;
        sum_rA  = fmaf(f, vr, sum_rA);
        nsum_iA = fmaf(f, vi, nsum_iA);
        upA = uc; hpA = hc; spvA = sc; cpvA = cc;
    };
    auto edgeB = [&](float uc, float hc, float sc, float cc) {
        const float du = uc - upB;
        const float dc = hc - hpB;
        const float rin = rcp_approx(du);
        const bool big = fabsf(du) >= EPS_U;
        const float m  = big ? rin : PI_F;
        const float f  = dc * m;
        const float vr = big ? (cpvB - cc) : spvB;
        const float vi = big ? (sc - spvB) : cpvB;
        sum_rB  = fmaf(f, vr, sum_rB);
        nsum_iB = fmaf(f, vi, nsum_iB);
        upB = uc; hpB = hc; spvB = sc; cpvB = cc;
    };

#pragma unroll 8
    for (int kk = 0; kk < NPTS / 2; ++kk) {
        const float4 pa = spA[kk];
        const float4 pb = spB[kk];
        float u0, h0, s0, c0, u1, h1, s1, c1;
        float u2, h2, s2, c2, u3, h3, s3, c3;
        // Four independent eval chains (2 points x 2 batches) -> ILP 4.
        eval1(pa.x, pa.y, u0, h0, s0, c0);
        eval1(pb.x, pb.y, u2, h2, s2, c2);
        eval1(pa.z, pa.w, u1, h1, s1, c1);
        eval1(pb.z, pb.w, u3, h3, s3, c3);
        edgeA(u0, h0, s0, c0);
        edgeB(u2, h2, s2, c2);
        edgeA(u1, h1, s1, c1);
        edgeB(u3, h3, s3, c3);
    }

    out[(b0 * 2 + 0) * N + n] = scale * sum_rA;
    out[(b0 * 2 + 1) * N + n] = -(scale * nsum_iA);
    out[(b1 * 2 + 0) * N + n] = scale * sum_rB;
    out[(b1 * 2 + 1) * N + n] = -(scale * nsum_iB);
}

extern "C" void kernel_launch(void* const* d_in, const int* in_sizes, int n_in,
                              void* d_out, int out_size) {
    const float* points = (const float*)d_in[0];  // [B, 64, 2] f32
    const float* phi    = (const float*)d_in[1];  // [N] f32
    float* out = (float*)d_out;                   // [B, 2, N] f32

    const int N = in_sizes[1];
    const int B = in_sizes[0] / (2 * NPTS);

    dim3 grid((N + BDIM - 1) / BDIM, B / 2);
    scatter_polygon_kernel<<<grid, BDIM>>>(points, phi, out, B, N);
}